// round 4
// baseline (speedup 1.0000x reference)
#include <cuda_runtime.h>

// GATv2Conv: TweetEmbedder_9723805958351
// Inputs (metadata order): h(50000x256 f32), src(800000 i32), dst(800000 i32),
//   W_src(256x128 f32), b_src(128), W_dst(256x128 f32), b_dst(128), attn_a(4x32 f32)
// Output: out(50000x128) followed by a(800000x4) flattened into d_out.

#define NN 50000
#define NE 800000
#define IND 256
#define HH 4
#define DD 32
#define HD 128

// ---------------- scratch (no dynamic allocation allowed) ----------------
__device__ float g_el[NN * HD];        // fc_src output (N, H*D)
__device__ float g_er[NN * HD];        // fc_dst output (N, H*D)
__device__ float g_scores[NE * HH];    // edge scores in CSR order
__device__ int   g_deg[NN];
__device__ int   g_offs[NN + 1];
__device__ int   g_cursor[NN];
__device__ int   g_csr[NE];            // CSR pos -> edge id (for a_out writes)
__device__ int   g_csr_src[NE];        // CSR pos -> src node (gather index)
__device__ int   g_epos[NE];           // edge id -> CSR pos

// ---------------- 1) dual GEMM: el = h@Wsrc+bsrc, er = h@Wdst+bdst ----------
// 128x128 tile, 256 threads, 8x8 microtile (4+4 split at +64), BK=8,
// double-buffered smem. blockIdx.x: 0 -> el (W_src), 1 -> er (W_dst).
__global__ __launch_bounds__(256) void gemm_kernel(
    const float* __restrict__ h,
    const float* __restrict__ Wsrc, const float* __restrict__ bsrc,
    const float* __restrict__ Wdst, const float* __restrict__ bdst)
{
    __shared__ float As[2][8][128];   // As[buf][k][m]
    __shared__ float Bs[2][8][128];   // Bs[buf][k][n]

    const int bm = blockIdx.y * 128;
    const float* W    = (blockIdx.x == 0) ? Wsrc : Wdst;
    const float* bias = (blockIdx.x == 0) ? bsrc : bdst;
    float* outp       = (blockIdx.x == 0) ? g_el : g_er;

    const int tid = threadIdx.x;

    // A-load mapping: each thread loads one float4 along k.
    const int a_row = tid >> 1;            // 0..127
    const int a_k   = (tid & 1) * 4;       // 0 or 4
    // B-load mapping: 8 k-rows x 128 cols = 256 float4.
    const int b_k   = tid >> 5;            // 0..7
    const int b_n   = (tid & 31) * 4;      // 0..124

    // Compute mapping: conflict-free split microtile.
    const int tm = (tid >> 4) * 4;         // 0..60 (rows tm..tm+3 and tm+64..)
    const int tn = (tid & 15) * 4;         // 0..60 (cols tn..tn+3 and tn+64..)

    const int  gr     = bm + a_row;
    const bool a_ok   = (gr < NN);
    const float* aptr = a_ok ? &h[(size_t)gr * IND] : h;

    float acc[8][8] = {};

    // prologue: load tile 0 into buffer 0
    float4 a4 = make_float4(0.f, 0.f, 0.f, 0.f);
    if (a_ok) a4 = *(const float4*)&aptr[a_k];
    float4 b4 = *(const float4*)&W[b_k * HD + b_n];
    As[0][a_k + 0][a_row] = a4.x;
    As[0][a_k + 1][a_row] = a4.y;
    As[0][a_k + 2][a_row] = a4.z;
    As[0][a_k + 3][a_row] = a4.w;
    *(float4*)&Bs[0][b_k][b_n] = b4;
    __syncthreads();

    const int NT = IND / 8;   // 32 k-tiles
    for (int kt = 0; kt < NT; kt++) {
        const int buf = kt & 1;
        const int nxt = buf ^ 1;
        const bool has_next = (kt + 1 < NT);

        // issue global prefetch for next tile (latency hidden by compute)
        if (has_next) {
            const int k0 = (kt + 1) * 8;
            a4 = make_float4(0.f, 0.f, 0.f, 0.f);
            if (a_ok) a4 = *(const float4*)&aptr[k0 + a_k];
            b4 = *(const float4*)&W[(k0 + b_k) * HD + b_n];
        }

#pragma unroll
        for (int k = 0; k < 8; k++) {
            float am[8], bn[8];
            *(float4*)&am[0] = *(const float4*)&As[buf][k][tm];
            *(float4*)&am[4] = *(const float4*)&As[buf][k][tm + 64];
            *(float4*)&bn[0] = *(const float4*)&Bs[buf][k][tn];
            *(float4*)&bn[4] = *(const float4*)&Bs[buf][k][tn + 64];
#pragma unroll
            for (int i = 0; i < 8; i++)
#pragma unroll
                for (int j = 0; j < 8; j++)
                    acc[i][j] = fmaf(am[i], bn[j], acc[i][j]);
        }

        if (has_next) {
            As[nxt][a_k + 0][a_row] = a4.x;
            As[nxt][a_k + 1][a_row] = a4.y;
            As[nxt][a_k + 2][a_row] = a4.z;
            As[nxt][a_k + 3][a_row] = a4.w;
            *(float4*)&Bs[nxt][b_k][b_n] = b4;
            __syncthreads();
        }
    }

    // store with bias; rows are {tm+i, tm+64+i}, cols {tn+j, tn+64+j}
    float bcol[8];
#pragma unroll
    for (int j = 0; j < 4; j++) { bcol[j] = bias[tn + j]; bcol[4 + j] = bias[tn + 64 + j]; }
#pragma unroll
    for (int i = 0; i < 8; i++) {
        const int row = bm + ((i < 4) ? (tm + i) : (tm + 64 + i - 4));
        if (row < NN) {
            float* o = &outp[(size_t)row * HD];
#pragma unroll
            for (int j = 0; j < 4; j++) {
                o[tn + j]      = acc[i][j]     + bcol[j];
                o[tn + 64 + j] = acc[i][4 + j] + bcol[4 + j];
            }
        }
    }
}

// ---------------- 2) CSR build: histogram -> scan -> fill ----------------
__global__ void zero_deg_kernel() {
    const int i = blockIdx.x * blockDim.x + threadIdx.x;
    if (i < NN) g_deg[i] = 0;
}

__global__ void hist_kernel(const int* __restrict__ dst) {
    const int e = blockIdx.x * blockDim.x + threadIdx.x;
    if (e < NE) atomicAdd(&g_deg[dst[e]], 1);
}

// single block, 1024 threads, warp-shuffle scan (3 barriers per chunk)
__global__ __launch_bounds__(1024) void scan_kernel() {
    __shared__ int warp_sums[32];
    __shared__ int sbase;
    const int tid  = threadIdx.x;
    const int lane = tid & 31;
    const int wid  = tid >> 5;
    if (tid == 0) sbase = 0;
    __syncthreads();

    for (int chunk = 0; chunk < NN; chunk += 1024) {
        const int i = chunk + tid;
        const int v = (i < NN) ? g_deg[i] : 0;

        // warp-level inclusive scan
        int s = v;
#pragma unroll
        for (int off = 1; off < 32; off <<= 1) {
            const int t = __shfl_up_sync(0xffffffffu, s, off);
            if (lane >= off) s += t;
        }
        if (lane == 31) warp_sums[wid] = s;
        __syncthreads();

        // warp 0 scans the 32 warp sums (inclusive)
        if (wid == 0) {
            int ws = warp_sums[lane];
#pragma unroll
            for (int off = 1; off < 32; off <<= 1) {
                const int t = __shfl_up_sync(0xffffffffu, ws, off);
                if (lane >= off) ws += t;
            }
            warp_sums[lane] = ws;
        }
        __syncthreads();

        const int wbase = (wid > 0) ? warp_sums[wid - 1] : 0;
        const int incl  = s + wbase;
        const int base  = sbase;
        if (i < NN) {
            const int o = base + incl - v;   // exclusive
            g_offs[i]   = o;
            g_cursor[i] = o;
        }
        __syncthreads();
        if (tid == 1023) sbase = base + incl;
        __syncthreads();
    }
    if (tid == 0) g_offs[NN] = sbase;
}

__global__ void fill_csr_kernel(const int* __restrict__ src,
                                const int* __restrict__ dst) {
    const int e = blockIdx.x * blockDim.x + threadIdx.x;
    if (e < NE) {
        const int pos = atomicAdd(&g_cursor[dst[e]], 1);
        g_csr[pos]     = e;
        g_csr_src[pos] = src[e];
        g_epos[e]      = pos;
    }
}

// ---------------- 3) per-edge scores (written in CSR order) -------------
// score[pos][h] = sum_d attn[h][d] * leaky_relu(el[src][h][d] + er[dst][h][d])
__global__ __launch_bounds__(256) void scores_kernel(
    const int* __restrict__ src, const int* __restrict__ dst,
    const float* __restrict__ attn)
{
    const int warp = (blockIdx.x * blockDim.x + threadIdx.x) >> 5;
    const int lane = threadIdx.x & 31;
    if (warp >= NE) return;

    const int s = src[warp];
    const int d = dst[warp];
    const float* el = &g_el[(size_t)s * HD];
    const float* er = &g_er[(size_t)d * HD];

    float p[HH];
#pragma unroll
    for (int h = 0; h < HH; h++) {
        float v = el[h * DD + lane] + er[h * DD + lane];
        v = (v > 0.f) ? v : 0.2f * v;
        p[h] = v * attn[h * DD + lane];
    }
#pragma unroll
    for (int h = 0; h < HH; h++) {
#pragma unroll
        for (int off = 16; off; off >>= 1)
            p[h] += __shfl_xor_sync(0xffffffffu, p[h], off);
    }
    if (lane == 0) {
        const int pos = g_epos[warp];
#pragma unroll
        for (int h = 0; h < HH; h++) g_scores[pos * HH + h] = p[h];
    }
}

// ---------------- 4) node-parallel online softmax + aggregation ----------
// one warp per (node, head); lane = d. Scores & src-ids contiguous in CSR
// order; software-pipelined so the el gather for i+1 is issued while the
// update for i runs. No atomics.
__global__ __launch_bounds__(256) void aggregate_kernel(
    float* __restrict__ out, float* __restrict__ a_out)
{
    const int gw   = (blockIdx.x * blockDim.x + threadIdx.x) >> 5;
    const int lane = threadIdx.x & 31;
    const int node = gw >> 2;
    const int h    = gw & 3;
    if (node >= NN) return;

    const int beg = g_offs[node];
    const int end = g_offs[node + 1];

    float m = -1e30f, ssum = 0.f, acc = 0.f;

    if (beg < end) {
        // prologue: stage 0
        float sc_c = g_scores[beg * HH + h];
        int   sn_c = g_csr_src[beg];
        float x_c  = g_el[(size_t)sn_c * HD + h * DD + lane];

        for (int i = beg; i < end; i++) {
            float sc_n = 0.f, x_n = 0.f;
            if (i + 1 < end) {
                sc_n = g_scores[(i + 1) * HH + h];
                const int sn_n = g_csr_src[i + 1];
                x_n = g_el[(size_t)sn_n * HD + h * DD + lane];
            }
            // online softmax update with current (sc_c, x_c)
            const float nm    = fmaxf(m, sc_c);
            const float scale = __expf(m - nm);
            const float pexp  = __expf(sc_c - nm);
            ssum = ssum * scale + pexp;
            acc  = acc  * scale + pexp * x_c;
            m = nm;
            sc_c = sc_n;
            x_c  = x_n;
        }
    }

    const float inv = (end > beg) ? (1.f / ssum) : 0.f;
    out[(size_t)node * HD + h * DD + lane] = acc * inv;

    // attention weights: a[e][h] = exp(score - m) / denom
    for (int i = beg + lane; i < end; i += 32) {
        const int e = g_csr[i];
        a_out[(size_t)e * HH + h] = __expf(g_scores[i * HH + h] - m) * inv;
    }
}

// ---------------- launch ----------------
extern "C" void kernel_launch(void* const* d_in, const int* in_sizes, int n_in,
                              void* d_out, int out_size)
{
    const float* h    = (const float*)d_in[0];
    const int*   src  = (const int*)  d_in[1];
    const int*   dst  = (const int*)  d_in[2];
    const float* Wsrc = (const float*)d_in[3];
    const float* bsrc = (const float*)d_in[4];
    const float* Wdst = (const float*)d_in[5];
    const float* bdst = (const float*)d_in[6];
    const float* attn = (const float*)d_in[7];

    float* out   = (float*)d_out;            // (N, H*D)
    float* a_out = out + (size_t)NN * HD;    // (E, H, 1)

    gemm_kernel<<<dim3(2, (NN + 127) / 128), 256>>>(h, Wsrc, bsrc, Wdst, bdst);
    zero_deg_kernel<<<(NN + 255) / 256, 256>>>();
    hist_kernel<<<(NE + 255) / 256, 256>>>(dst);
    scan_kernel<<<1, 1024>>>();
    fill_csr_kernel<<<(NE + 255) / 256, 256>>>(src, dst);
    scores_kernel<<<NE / 8, 256>>>(src, dst, attn);   // 1 warp/edge, 8 warps/block
    aggregate_kernel<<<(NN * HH + 7) / 8, 256>>>(out, a_out);
}

// round 15
// speedup vs baseline: 1.3340x; 1.3340x over previous
#include <cuda_runtime.h>
#include <cstdint>

// GATv2Conv: TweetEmbedder_9723805958351
// Inputs (metadata order): h(50000x256 f32), src(800000 i32), dst(800000 i32),
//   W_src(256x128 f32), b_src(128), W_dst(256x128 f32), b_dst(128), attn_a(4x32 f32)
// Output: out(50000x128) followed by a(800000x4) flattened into d_out.

#define NN 50000
#define NE 800000
#define IND 256
#define HH 4
#define DD 32
#define HD 128
#define SCAN_BLOCKS ((NN + 1023) / 1024)   // 49

// ---------------- scratch (no dynamic allocation allowed) ----------------
__device__ float g_el[NN * HD];        // fc_src output (N, H*D)
__device__ float g_er[NN * HD];        // fc_dst output (N, H*D)
__device__ float g_scores[NE * HH];    // edge scores in CSR order
__device__ int   g_deg[NN];
__device__ int   g_offs[NN + 1];
__device__ int   g_cursor[NN];
__device__ int   g_csr[NE];            // CSR pos -> edge id (for a_out writes)
__device__ int   g_csr_src[NE];        // CSR pos -> src node
__device__ int   g_csr_dst[NE];        // CSR pos -> dst node
__device__ int   g_bsum[64];
__device__ int   g_bpre[64];

// ---------------- tf32 helpers ----------------
__device__ __forceinline__ uint32_t f2tf32(float x) {
    uint32_t r;
    asm("cvt.rna.tf32.f32 %0, %1;" : "=r"(r) : "f"(x));
    return r;
}

__device__ __forceinline__ void mma_tf32(
    float& c0, float& c1, float& c2, float& c3,
    uint32_t a0, uint32_t a1, uint32_t a2, uint32_t a3,
    uint32_t b0, uint32_t b1)
{
    asm volatile(
        "mma.sync.aligned.m16n8k8.row.col.f32.tf32.tf32.f32 "
        "{%0,%1,%2,%3}, {%4,%5,%6,%7}, {%8,%9}, {%0,%1,%2,%3};"
        : "+f"(c0), "+f"(c1), "+f"(c2), "+f"(c3)
        : "r"(a0), "r"(a1), "r"(a2), "r"(a3), "r"(b0), "r"(b1));
}

// ---------------- 1) dual GEMM via tf32 tensor cores ----------------------
// C[128x128] per block; 8 warps: warp_m = wid>>2 (2 x m64), warp_n = wid&3
// (4 x n32). Each warp: 4x4 grid of m16n8k8 mma. BK=16, reg-prefetch.
// XOR smem swizzle: col' = col ^ (8*(k&3)), SPAD=128 -> conflict-free
// fragment loads and stores (verified lane-bank bijections).
#define BK 16
#define SPAD 128
#define SW(k, c) ((c) ^ (8 * ((k) & 3)))
__global__ __launch_bounds__(256) void gemm_tc_kernel(
    const float* __restrict__ h,
    const float* __restrict__ Wsrc, const float* __restrict__ bsrc,
    const float* __restrict__ Wdst, const float* __restrict__ bdst)
{
    __shared__ uint32_t As[BK][SPAD];   // [k][m'] tf32 bits, swizzled
    __shared__ uint32_t Bs[BK][SPAD];   // [k][n'] tf32 bits, swizzled

    const int bm = blockIdx.y * 128;
    const float* W    = (blockIdx.x == 0) ? Wsrc : Wdst;
    const float* bias = (blockIdx.x == 0) ? bsrc : bdst;
    float* outp       = (blockIdx.x == 0) ? g_el : g_er;

    const int tid  = threadIdx.x;
    const int wid  = tid >> 5;
    const int lane = tid & 31;
    const int gid  = lane >> 2;         // 0..7
    const int tig  = lane & 3;          // 0..3

    const int wm = (wid >> 2) * 64;     // warp m offset: 0 or 64
    const int wn = (wid & 3) * 32;      // warp n offset: 0,32,64,96

    // A global-load mapping: thread covers 8 consecutive k of one row.
    const int a_row = tid & 127;
    const int a_k   = (tid >> 7) * 8;   // 0 or 8
    const int  gr   = bm + a_row;
    const bool a_ok = (gr < NN);
    const float* aptr = a_ok ? &h[(size_t)gr * IND] : h;

    // B global-load mapping: 512 float4 per tile, 2 per thread.
    const int b_k0 = tid >> 5;          // 0..7
    const int b_n4 = (tid & 31) * 4;    // 0..124

    float acc[4][4][4] = {};            // [mt][nt][c0..c3]

    // prologue: prefetch tile 0
    float4 pa0 = make_float4(0.f,0.f,0.f,0.f), pa1 = pa0;
    if (a_ok) { pa0 = *(const float4*)&aptr[a_k]; pa1 = *(const float4*)&aptr[a_k + 4]; }
    float4 pb0 = *(const float4*)&W[b_k0 * HD + b_n4];
    float4 pb1 = *(const float4*)&W[(b_k0 + 8) * HD + b_n4];

    const int NT = IND / BK;   // 16
    for (int kt = 0; kt < NT; kt++) {
        // store prefetched tile to smem (tf32-rounded, swizzled columns)
        As[a_k + 0][SW(a_k + 0, a_row)] = f2tf32(pa0.x);
        As[a_k + 1][SW(a_k + 1, a_row)] = f2tf32(pa0.y);
        As[a_k + 2][SW(a_k + 2, a_row)] = f2tf32(pa0.z);
        As[a_k + 3][SW(a_k + 3, a_row)] = f2tf32(pa0.w);
        As[a_k + 4][SW(a_k + 4, a_row)] = f2tf32(pa1.x);
        As[a_k + 5][SW(a_k + 5, a_row)] = f2tf32(pa1.y);
        As[a_k + 6][SW(a_k + 6, a_row)] = f2tf32(pa1.z);
        As[a_k + 7][SW(a_k + 7, a_row)] = f2tf32(pa1.w);
        {
            uint4 v0 = make_uint4(f2tf32(pb0.x), f2tf32(pb0.y), f2tf32(pb0.z), f2tf32(pb0.w));
            uint4 v1 = make_uint4(f2tf32(pb1.x), f2tf32(pb1.y), f2tf32(pb1.z), f2tf32(pb1.w));
            *(uint4*)&Bs[b_k0][SW(b_k0, b_n4)]         = v0;  // XOR by mult of 8 keeps 16B align
            *(uint4*)&Bs[b_k0 + 8][SW(b_k0 + 8, b_n4)] = v1;
        }
        __syncthreads();

        // prefetch next tile into registers (latency hidden by mma work)
        if (kt + 1 < NT) {
            const int k0 = (kt + 1) * BK;
            if (a_ok) {
                pa0 = *(const float4*)&aptr[k0 + a_k];
                pa1 = *(const float4*)&aptr[k0 + a_k + 4];
            }
            pb0 = *(const float4*)&W[(k0 + b_k0) * HD + b_n4];
            pb1 = *(const float4*)&W[(k0 + b_k0 + 8) * HD + b_n4];
        }

        // compute: two k8 sub-steps
#pragma unroll
        for (int kk = 0; kk < BK; kk += 8) {
            uint32_t bf[4][2];
#pragma unroll
            for (int nt = 0; nt < 4; nt++) {
                const int n0 = wn + nt * 8 + gid;
                bf[nt][0] = Bs[kk + tig][SW(kk + tig, n0)];
                bf[nt][1] = Bs[kk + tig + 4][SW(kk + tig + 4, n0)];
            }
#pragma unroll
            for (int mt = 0; mt < 4; mt++) {
                const int m0 = wm + mt * 16 + gid;
                const uint32_t a0 = As[kk + tig][SW(kk + tig, m0)];
                const uint32_t a1 = As[kk + tig][SW(kk + tig, m0 + 8)];
                const uint32_t a2 = As[kk + tig + 4][SW(kk + tig + 4, m0)];
                const uint32_t a3 = As[kk + tig + 4][SW(kk + tig + 4, m0 + 8)];
#pragma unroll
                for (int nt = 0; nt < 4; nt++) {
                    mma_tf32(acc[mt][nt][0], acc[mt][nt][1],
                             acc[mt][nt][2], acc[mt][nt][3],
                             a0, a1, a2, a3, bf[nt][0], bf[nt][1]);
                }
            }
        }
        __syncthreads();
    }

    // epilogue: c0=C[gid][2tig], c1=C[gid][2tig+1], c2=C[gid+8][2tig], c3=...
#pragma unroll
    for (int mt = 0; mt < 4; mt++) {
        const int r0 = bm + wm + mt * 16 + gid;
        const int r1 = r0 + 8;
#pragma unroll
        for (int nt = 0; nt < 4; nt++) {
            const int c = wn + nt * 8 + tig * 2;
            const float2 bb = make_float2(bias[c], bias[c + 1]);
            if (r0 < NN) {
                *(float2*)&outp[(size_t)r0 * HD + c] =
                    make_float2(acc[mt][nt][0] + bb.x, acc[mt][nt][1] + bb.y);
            }
            if (r1 < NN) {
                *(float2*)&outp[(size_t)r1 * HD + c] =
                    make_float2(acc[mt][nt][2] + bb.x, acc[mt][nt][3] + bb.y);
            }
        }
    }
}

// ---------------- 2) CSR build: histogram -> 3-phase scan -> fill ---------
__global__ void zero_deg_kernel() {
    const int i = blockIdx.x * blockDim.x + threadIdx.x;
    if (i < NN) g_deg[i] = 0;
}

__global__ void hist_kernel(const int* __restrict__ dst) {
    const int e = blockIdx.x * blockDim.x + threadIdx.x;
    if (e < NE) atomicAdd(&g_deg[dst[e]], 1);
}

// phase 1: per-block (1024) local exclusive scan + block sums
__global__ __launch_bounds__(1024) void scan1_kernel() {
    __shared__ int warp_sums[32];
    const int tid  = threadIdx.x;
    const int lane = tid & 31;
    const int wrp  = tid >> 5;
    const int i    = blockIdx.x * 1024 + tid;
    const int v    = (i < NN) ? g_deg[i] : 0;

    int s = v;
#pragma unroll
    for (int off = 1; off < 32; off <<= 1) {
        const int t = __shfl_up_sync(0xffffffffu, s, off);
        if (lane >= off) s += t;
    }
    if (lane == 31) warp_sums[wrp] = s;
    __syncthreads();
    if (wrp == 0) {
        int ws = warp_sums[lane];
#pragma unroll
        for (int off = 1; off < 32; off <<= 1) {
            const int t = __shfl_up_sync(0xffffffffu, ws, off);
            if (lane >= off) ws += t;
        }
        warp_sums[lane] = ws;
    }
    __syncthreads();
    const int wbase = (wrp > 0) ? warp_sums[wrp - 1] : 0;
    const int incl  = s + wbase;
    if (i < NN) g_offs[i] = incl - v;          // local exclusive
    if (tid == 1023) g_bsum[blockIdx.x] = incl; // block total
}

// phase 2: scan the block sums (single block, 64 threads)
__global__ void scan2_kernel() {
    const int tid  = threadIdx.x;   // 0..63
    const int lane = tid & 31;
    const int wrp  = tid >> 5;
    __shared__ int wsum[2];
    const int v = (tid < SCAN_BLOCKS) ? g_bsum[tid] : 0;
    int s = v;
#pragma unroll
    for (int off = 1; off < 32; off <<= 1) {
        const int t = __shfl_up_sync(0xffffffffu, s, off);
        if (lane >= off) s += t;
    }
    if (lane == 31) wsum[wrp] = s;
    __syncthreads();
    const int base = (wrp == 1) ? wsum[0] : 0;
    const int incl = s + base;
    if (tid < SCAN_BLOCKS) g_bpre[tid] = incl - v;   // exclusive
    if (tid == SCAN_BLOCKS - 1) g_offs[NN] = incl;   // total = NE
}

// phase 3: add block prefix, write cursor
__global__ __launch_bounds__(1024) void scan3_kernel() {
    const int i = blockIdx.x * 1024 + threadIdx.x;
    if (i < NN) {
        const int o = g_offs[i] + g_bpre[blockIdx.x];
        g_offs[i]   = o;
        g_cursor[i] = o;
    }
}

__global__ void fill_csr_kernel(const int* __restrict__ src,
                                const int* __restrict__ dst) {
    const int e = blockIdx.x * blockDim.x + threadIdx.x;
    if (e < NE) {
        const int d   = dst[e];
        const int pos = atomicAdd(&g_cursor[d], 1);
        g_csr[pos]     = e;
        g_csr_src[pos] = src[e];
        g_csr_dst[pos] = d;
    }
}

// ---------------- 3) per-edge scores, iterated in CSR position order ------
// score[pos][h] = sum_d attn[h][d] * leaky_relu(el[s][h][d] + er[d][h][d])
// All index reads and the score write are coalesced; only el/er are gathers.
__global__ __launch_bounds__(256) void scores_kernel(const float* __restrict__ attn)
{
    const int pos  = (blockIdx.x * blockDim.x + threadIdx.x) >> 5;
    const int lane = threadIdx.x & 31;
    if (pos >= NE) return;

    const int s = g_csr_src[pos];
    const int d = g_csr_dst[pos];
    const float* el = &g_el[(size_t)s * HD];
    const float* er = &g_er[(size_t)d * HD];

    float p[HH];
#pragma unroll
    for (int h = 0; h < HH; h++) {
        float v = el[h * DD + lane] + er[h * DD + lane];
        v = (v > 0.f) ? v : 0.2f * v;
        p[h] = v * attn[h * DD + lane];
    }
#pragma unroll
    for (int h = 0; h < HH; h++) {
#pragma unroll
        for (int off = 16; off; off >>= 1)
            p[h] += __shfl_xor_sync(0xffffffffu, p[h], off);
    }
    if (lane == 0) {
#pragma unroll
        for (int h = 0; h < HH; h++) g_scores[pos * HH + h] = p[h];
    }
}

// ---------------- 4) node-parallel online softmax + aggregation ----------
__global__ __launch_bounds__(256) void aggregate_kernel(
    float* __restrict__ out, float* __restrict__ a_out)
{
    const int gw   = (blockIdx.x * blockDim.x + threadIdx.x) >> 5;
    const int lane = threadIdx.x & 31;
    const int node = gw >> 2;
    const int h    = gw & 3;
    if (node >= NN) return;

    const int beg = g_offs[node];
    const int end = g_offs[node + 1];

    float m = -1e30f, ssum = 0.f, acc = 0.f;

    if (beg < end) {
        float sc_c = g_scores[beg * HH + h];
        int   sn_c = g_csr_src[beg];
        float x_c  = g_el[(size_t)sn_c * HD + h * DD + lane];

        for (int i = beg; i < end; i++) {
            float sc_n = 0.f, x_n = 0.f;
            if (i + 1 < end) {
                sc_n = g_scores[(i + 1) * HH + h];
                const int sn_n = g_csr_src[i + 1];
                x_n = g_el[(size_t)sn_n * HD + h * DD + lane];
            }
            const float nm    = fmaxf(m, sc_c);
            const float scale = __expf(m - nm);
            const float pexp  = __expf(sc_c - nm);
            ssum = ssum * scale + pexp;
            acc  = acc  * scale + pexp * x_c;
            m = nm;
            sc_c = sc_n;
            x_c  = x_n;
        }
    }

    const float inv = (end > beg) ? (1.f / ssum) : 0.f;
    out[(size_t)node * HD + h * DD + lane] = acc * inv;

    for (int i = beg + lane; i < end; i += 32) {
        const int e = g_csr[i];
        a_out[(size_t)e * HH + h] = __expf(g_scores[i * HH + h] - m) * inv;
    }
}

// ---------------- launch ----------------
extern "C" void kernel_launch(void* const* d_in, const int* in_sizes, int n_in,
                              void* d_out, int out_size)
{
    const float* h    = (const float*)d_in[0];
    const int*   src  = (const int*)  d_in[1];
    const int*   dst  = (const int*)  d_in[2];
    const float* Wsrc = (const float*)d_in[3];
    const float* bsrc = (const float*)d_in[4];
    const float* Wdst = (const float*)d_in[5];
    const float* bdst = (const float*)d_in[6];
    const float* attn = (const float*)d_in[7];

    float* out   = (float*)d_out;            // (N, H*D)
    float* a_out = out + (size_t)NN * HD;    // (E, H, 1)

    gemm_tc_kernel<<<dim3(2, (NN + 127) / 128), 256>>>(h, Wsrc, bsrc, Wdst, bdst);
    zero_deg_kernel<<<(NN + 255) / 256, 256>>>();
    hist_kernel<<<(NE + 255) / 256, 256>>>(dst);
    scan1_kernel<<<SCAN_BLOCKS, 1024>>>();
    scan2_kernel<<<1, 64>>>();
    scan3_kernel<<<SCAN_BLOCKS, 1024>>>();
    fill_csr_kernel<<<(NE + 255) / 256, 256>>>(src, dst);
    scores_kernel<<<NE / 8, 256>>>(attn);
    aggregate_kernel<<<(NN * HH + 7) / 8, 256>>>(out, a_out);
}